// round 4
// baseline (speedup 1.0000x reference)
#include <cuda_runtime.h>

// DempsterSchaferCombine — algebraically reduced to a pure elementwise stream:
//   out = (a1-1)*(a2-1)/21 + a1 + a2 - 1
// (Dirichlet strengths S1,S2 and the conflict denom cancel exactly; rel_err
// vs the full reference path is ~8e-8.)
//
// R4: n4 = 11,010,048 = 21504 blocks * 512 float4 exactly -> branch-free
// exact-tiling kernel (no bounds predicates). Guarded fallback kernel kept
// for non-divisible shapes, chosen host-side. 2 block-contiguous float4 per
// thread, 4 independent LDG.128.CS front-batched, regs <=32 via
// __launch_bounds__(256,8) to hold 2048 thr/SM.

#define INV_C (1.0f / 21.0f)

__device__ __forceinline__ float4 ds4(float4 x, float4 y) {
    float4 r;
    r.x = fmaf((x.x - 1.0f) * (y.x - 1.0f), INV_C, x.x + y.x - 1.0f);
    r.y = fmaf((x.y - 1.0f) * (y.y - 1.0f), INV_C, x.y + y.y - 1.0f);
    r.z = fmaf((x.z - 1.0f) * (y.z - 1.0f), INV_C, x.z + y.z - 1.0f);
    r.w = fmaf((x.w - 1.0f) * (y.w - 1.0f), INV_C, x.w + y.w - 1.0f);
    return r;
}

// Exact path: every block owns 512 contiguous float4, no predicates.
__global__ __launch_bounds__(256, 8) void ds_combine_exact(
    const float4* __restrict__ a1,
    const float4* __restrict__ a2,
    float4* __restrict__ out)
{
    int i0 = blockIdx.x * 512 + threadIdx.x;
    int i1 = i0 + 256;

    float4 x0 = __ldcs(a1 + i0);
    float4 x1 = __ldcs(a1 + i1);
    float4 y0 = __ldcs(a2 + i0);
    float4 y1 = __ldcs(a2 + i1);

    __stcs(out + i0, ds4(x0, y0));
    __stcs(out + i1, ds4(x1, y1));
}

// Guarded fallback for shapes where n4 % 512 != 0.
__global__ __launch_bounds__(256, 8) void ds_combine_guarded(
    const float4* __restrict__ a1,
    const float4* __restrict__ a2,
    float4* __restrict__ out,
    int n4)
{
    int i0 = blockIdx.x * 512 + threadIdx.x;
    int i1 = i0 + 256;

    if (i1 < n4) {
        float4 x0 = __ldcs(a1 + i0);
        float4 x1 = __ldcs(a1 + i1);
        float4 y0 = __ldcs(a2 + i0);
        float4 y1 = __ldcs(a2 + i1);
        __stcs(out + i0, ds4(x0, y0));
        __stcs(out + i1, ds4(x1, y1));
    } else if (i0 < n4) {
        float4 x0 = __ldcs(a1 + i0);
        float4 y0 = __ldcs(a2 + i0);
        __stcs(out + i0, ds4(x0, y0));
    }
}

// Scalar tail for n % 4 != 0 (not hit for this shape; kept for safety).
__global__ void ds_combine_tail(
    const float* __restrict__ a1,
    const float* __restrict__ a2,
    float* __restrict__ out,
    int start, int n)
{
    int i = start + blockIdx.x * blockDim.x + threadIdx.x;
    if (i >= n) return;
    float x = a1[i], y = a2[i];
    out[i] = fmaf((x - 1.0f) * (y - 1.0f), INV_C, x + y - 1.0f);
}

extern "C" void kernel_launch(void* const* d_in, const int* in_sizes, int n_in,
                              void* d_out, int out_size)
{
    const float* a1 = (const float*)d_in[0];
    const float* a2 = (const float*)d_in[1];
    float* out = (float*)d_out;

    int n = out_size;          // 8*21*512*512 = 44,040,192
    int n4 = n >> 2;           // 11,010,048 float4

    const int threads = 256;
    const int f4_per_block = 512;

    if (n4 % f4_per_block == 0) {
        // This shape: 21504 full blocks, branch-free.
        ds_combine_exact<<<n4 / f4_per_block, threads>>>(
            (const float4*)a1, (const float4*)a2, (float4*)out);
    } else {
        int blocks = (n4 + f4_per_block - 1) / f4_per_block;
        ds_combine_guarded<<<blocks, threads>>>(
            (const float4*)a1, (const float4*)a2, (float4*)out, n4);
    }

    int tail_start = n4 << 2;
    if (n - tail_start > 0) {
        ds_combine_tail<<<1, 128>>>(a1, a2, out, tail_start, n);
    }
}